// round 1
// baseline (speedup 1.0000x reference)
#include <cuda_runtime.h>
#include <cstdint>

#define HID 512
#define BAT 32
#define TLEN 512
#define G4 2048
#define NBLK 128
#define PITCH 36   // smem row pitch in floats (k-major layouts), 16B aligned, bank-staggered

// ----------------------------------------------------------------------------
// Scratch (static __device__ — no allocations allowed)
// ----------------------------------------------------------------------------
__device__ float g_xg[2][TLEN][BAT][G4];       // 256 MB: xg[dir][t][b][gate]
__device__ float g_hbuf[2][2][BAT][HID];       // [parity][dir][b][j]
__device__ unsigned g_bar_cnt;
__device__ volatile unsigned g_bar_gen;

// ----------------------------------------------------------------------------
// Kernel 1: xg[dir][t][b][g] = sum_k x[b][t][k] * Wih[g][k] + bih[g] + bhh[g]
// Classic 128x128x16 tiled SGEMM, 256 threads, 8x8 register tiles.
// A = x viewed as [M=16384, K=512] with m = b*512 + t (rows contiguous in k).
// B = Wih [N=2048, K=512].
// ----------------------------------------------------------------------------
__global__ void __launch_bounds__(256) gemm_xg_kernel(
    const float* __restrict__ A,
    const float* __restrict__ W,
    const float* __restrict__ bih,
    const float* __restrict__ bhh,
    int dir)
{
    __shared__ float As[16][132];
    __shared__ float Bs[16][132];

    const int m0 = blockIdx.y * 128;
    const int n0 = blockIdx.x * 128;
    const int tid = threadIdx.x;
    const int tx = tid & 15;
    const int ty = tid >> 4;
    const int lrow = tid >> 2;          // 0..63
    const int lkc  = (tid & 3) * 4;     // 0,4,8,12

    float acc[8][8];
    #pragma unroll
    for (int i = 0; i < 8; i++)
        #pragma unroll
        for (int j = 0; j < 8; j++) acc[i][j] = 0.f;

    for (int k0 = 0; k0 < 512; k0 += 16) {
        #pragma unroll
        for (int u = 0; u < 2; u++) {
            int row = lrow + u * 64;
            float4 av = *(const float4*)&A[(size_t)(m0 + row) * 512 + k0 + lkc];
            As[lkc + 0][row] = av.x; As[lkc + 1][row] = av.y;
            As[lkc + 2][row] = av.z; As[lkc + 3][row] = av.w;
            float4 bv = *(const float4*)&W[(size_t)(n0 + row) * 512 + k0 + lkc];
            Bs[lkc + 0][row] = bv.x; Bs[lkc + 1][row] = bv.y;
            Bs[lkc + 2][row] = bv.z; Bs[lkc + 3][row] = bv.w;
        }
        __syncthreads();
        #pragma unroll
        for (int k = 0; k < 16; k++) {
            float a[8], b[8];
            *(float4*)&a[0] = *(const float4*)&As[k][ty * 8];
            *(float4*)&a[4] = *(const float4*)&As[k][ty * 8 + 4];
            *(float4*)&b[0] = *(const float4*)&Bs[k][tx * 8];
            *(float4*)&b[4] = *(const float4*)&Bs[k][tx * 8 + 4];
            #pragma unroll
            for (int i = 0; i < 8; i++)
                #pragma unroll
                for (int j = 0; j < 8; j++)
                    acc[i][j] = fmaf(a[i], b[j], acc[i][j]);
        }
        __syncthreads();
    }

    float bias[8];
    #pragma unroll
    for (int j = 0; j < 8; j++) {
        int n = n0 + tx * 8 + j;
        bias[j] = bih[n] + bhh[n];
    }
    #pragma unroll
    for (int i = 0; i < 8; i++) {
        int m = m0 + ty * 8 + i;
        int t = m & 511;
        int b = m >> 9;
        float* o = &g_xg[dir][t][b][n0 + tx * 8];
        float4 v0 = make_float4(acc[i][0] + bias[0], acc[i][1] + bias[1],
                                acc[i][2] + bias[2], acc[i][3] + bias[3]);
        float4 v1 = make_float4(acc[i][4] + bias[4], acc[i][5] + bias[5],
                                acc[i][6] + bias[6], acc[i][7] + bias[7]);
        *(float4*)&o[0] = v0;
        *(float4*)&o[4] = v1;
    }
}

// ----------------------------------------------------------------------------
// Graph-replay-safe grid barrier (generation counting). All 128 blocks are
// co-resident (1 block/SM by smem), so no deadlock.
// ----------------------------------------------------------------------------
__device__ __forceinline__ void grid_barrier()
{
    __threadfence();
    __syncthreads();
    if (threadIdx.x == 0) {
        unsigned gen = g_bar_gen;
        unsigned ticket = atomicAdd(&g_bar_cnt, 1u);
        if (ticket == NBLK - 1u) {
            g_bar_cnt = 0u;
            __threadfence();
            g_bar_gen = gen + 1u;
        } else {
            while (g_bar_gen == gen) { }
        }
        __threadfence();
    }
    __syncthreads();
}

__device__ __forceinline__ float fsigmoid(float x)
{
    return 1.f / (1.f + __expf(-x));
}

// ----------------------------------------------------------------------------
// Kernel 2: persistent scan. 128 blocks: dir = blk/64, hidden slice of 8 units.
// smem: Wt[512][36] (Whh slice, k-major), ht[512][36] (h, k-major),
//       red[8][32][36] (cross-k partial reduction).
// Per step: 32 gate-rows x 32 batches dots of length 512.
// Thread map (matmul): ks = tid/16 (16 k-chunks, strided k = kk*16+ks),
//                      rg = (tid%16)/4 -> rows rg*8..+7, bg = tid%4 -> batches bg*8..+7.
// Warp-level shfl folds 2 k-chunks -> 8 partials in red.
// Thread map (finalize): fb = tid/8 (batch), fj = tid%8 (hidden unit).
// ----------------------------------------------------------------------------
#define SMEM_FLOATS (2 * 512 * PITCH + 8 * 32 * PITCH)   // 46080 floats = 184320 B

__global__ void __launch_bounds__(256, 1) lstm_scan_kernel(
    const float* __restrict__ Whh_f,
    const float* __restrict__ Whh_b,
    float* __restrict__ out)
{
    extern __shared__ float sm[];
    float* Wt  = sm;                       // [512][PITCH]
    float* ht  = sm + 512 * PITCH;         // [512][PITCH]
    float* red = sm + 2 * 512 * PITCH;     // [8][32][PITCH]

    const int tid = threadIdx.x;
    const int dir = blockIdx.x >> 6;
    const int j0  = (blockIdx.x & 63) * 8;
    const float* __restrict__ Whh = dir ? Whh_b : Whh_f;

    // Load + transpose Whh slice into Wt[k][r], local col r = s*8 + jj.
    {
        int r = tid & 31;
        int gr = (r >> 3) * 512 + j0 + (r & 7);
        const float* src = Whh + (size_t)gr * 512;
        int k0 = (tid >> 5) * 64;
        for (int k = k0; k < k0 + 64; k += 4) {
            float4 v = *(const float4*)&src[k];
            Wt[(k + 0) * PITCH + r] = v.x;
            Wt[(k + 1) * PITCH + r] = v.y;
            Wt[(k + 2) * PITCH + r] = v.z;
            Wt[(k + 3) * PITCH + r] = v.w;
        }
    }
    // h_{-1} = 0
    for (int i = tid; i < 512 * PITCH; i += 256) ht[i] = 0.f;

    const int ks = tid >> 4;          // 0..15
    const int w  = tid & 15;
    const int rg = w >> 2;            // 0..3
    const int bg = w & 3;             // 0..3
    const int warp = tid >> 5;        // 0..7
    const int fb = tid >> 3;          // 0..31 (finalize batch)
    const int fj = tid & 7;           // 0..7  (finalize hidden unit)
    float c_state = 0.f;

    __syncthreads();

    for (int s = 0; s < 512; s++) {
        const int t = dir ? (511 - s) : s;

        // ---- matmul: D[r][b] = sum_k Wt[k][r] * ht[k][b] (thread: 8x8 tile, 1/16 k)
        float acc[8][8];
        #pragma unroll
        for (int i = 0; i < 8; i++)
            #pragma unroll
            for (int j = 0; j < 8; j++) acc[i][j] = 0.f;

        const float* wp = Wt + rg * 8;
        const float* hp = ht + bg * 8;
        #pragma unroll 4
        for (int kk = 0; kk < 32; kk++) {
            int ko = (kk * 16 + ks) * PITCH;
            float a[8], hb[8];
            *(float4*)&a[0]  = *(const float4*)&wp[ko];
            *(float4*)&a[4]  = *(const float4*)&wp[ko + 4];
            *(float4*)&hb[0] = *(const float4*)&hp[ko];
            *(float4*)&hb[4] = *(const float4*)&hp[ko + 4];
            #pragma unroll
            for (int i = 0; i < 8; i++)
                #pragma unroll
                for (int j = 0; j < 8; j++)
                    acc[i][j] = fmaf(a[i], hb[j], acc[i][j]);
        }

        // fold k-chunk pairs within each warp (lane ^ 16 is same tile, other ks parity)
        #pragma unroll
        for (int i = 0; i < 8; i++)
            #pragma unroll
            for (int j = 0; j < 8; j++)
                acc[i][j] += __shfl_xor_sync(0xffffffffu, acc[i][j], 16);

        if ((tid & 16) == 0) {
            #pragma unroll
            for (int i = 0; i < 8; i++) {
                int rho = i * 4 + rg;      // permuted row index (bank-stagger)
                float* rp = red + warp * (32 * PITCH) + rho * PITCH + bg * 8;
                *(float4*)&rp[0] = make_float4(acc[i][0], acc[i][1], acc[i][2], acc[i][3]);
                *(float4*)&rp[4] = make_float4(acc[i][4], acc[i][5], acc[i][6], acc[i][7]);
            }
        }
        __syncthreads();

        // ---- finalize: thread (fb, fj) owns one (batch, hidden) cell
        {
            float d0 = 0.f, d1 = 0.f, d2 = 0.f, d3 = 0.f;
            #pragma unroll
            for (int wv = 0; wv < 8; wv++) {
                const float* rp = red + wv * (32 * PITCH) + fb;
                d0 += rp[(fj * 4 + 0) * PITCH];   // rho for r = 0*8+fj
                d1 += rp[(fj * 4 + 1) * PITCH];   // rho for r = 1*8+fj
                d2 += rp[(fj * 4 + 2) * PITCH];   // rho for r = 2*8+fj
                d3 += rp[(fj * 4 + 3) * PITCH];   // rho for r = 3*8+fj
            }
            const float* xgp = &g_xg[dir][t][fb][0];
            float pi = xgp[         j0 + fj] + d0;
            float pf = xgp[ 512 +   j0 + fj] + d1;
            float pg = xgp[1024 +   j0 + fj] + d2;
            float po = xgp[1536 +   j0 + fj] + d3;

            float ig = fsigmoid(pi);
            float fg = fsigmoid(pf);
            float gg = tanhf(pg);
            float og = fsigmoid(po);
            c_state = fg * c_state + ig * gg;
            float hval = og * tanhf(c_state);

            out[(size_t)fb * (TLEN * 1024) + (size_t)t * 1024 + dir * 512 + j0 + fj] = hval;
            g_hbuf[s & 1][dir][fb][j0 + fj] = hval;
        }

        if (s < 511) {
            grid_barrier();
            // reload full h for this direction (transpose into ht[k][b])
            int b  = tid & 31;
            int k0 = (tid >> 5) * 64;
            const float* src = &g_hbuf[s & 1][dir][b][0];
            for (int k = k0; k < k0 + 64; k += 4) {
                float4 v = *(const float4*)&src[k];
                ht[(k + 0) * PITCH + b] = v.x;
                ht[(k + 1) * PITCH + b] = v.y;
                ht[(k + 2) * PITCH + b] = v.z;
                ht[(k + 3) * PITCH + b] = v.w;
            }
            __syncthreads();
        }
    }
}

// ----------------------------------------------------------------------------
// Launch
// ----------------------------------------------------------------------------
extern "C" void kernel_launch(void* const* d_in, const int* in_sizes, int n_in,
                              void* d_out, int out_size)
{
    (void)in_sizes; (void)n_in; (void)out_size;
    const float* x     = (const float*)d_in[0];
    const float* Wih_f = (const float*)d_in[1];
    const float* Whh_f = (const float*)d_in[2];
    const float* bih_f = (const float*)d_in[3];
    const float* bhh_f = (const float*)d_in[4];
    const float* Wih_b = (const float*)d_in[5];
    const float* Whh_b = (const float*)d_in[6];
    const float* bih_b = (const float*)d_in[7];
    const float* bhh_b = (const float*)d_in[8];
    float* out = (float*)d_out;

    static bool attr_set = false;
    if (!attr_set) {
        cudaFuncSetAttribute(lstm_scan_kernel,
                             cudaFuncAttributeMaxDynamicSharedMemorySize,
                             SMEM_FLOATS * (int)sizeof(float));
        attr_set = true;
    }

    dim3 ggrid(16, 128);
    gemm_xg_kernel<<<ggrid, 256>>>(x, Wih_f, bih_f, bhh_f, 0);
    gemm_xg_kernel<<<ggrid, 256>>>(x, Wih_b, bih_b, bhh_b, 1);
    lstm_scan_kernel<<<NBLK, 256, SMEM_FLOATS * sizeof(float)>>>(Whh_f, Whh_b, out);
}